// round 3
// baseline (speedup 1.0000x reference)
#include <cuda_runtime.h>
#include <cuda_fp8.h>
#include <stdint.h>

#define DI __device__ __forceinline__

// ---------------- problem constants ----------------
constexpr int M_DIM = 4096;
constexpr int K_DIM = 4096;
constexpr int N_DIM = 16384;

// ---------------- GEMM tiling ----------------
constexpr int MT = 128;          // CTA M tile
constexpr int NT = 256;          // CTA N tile
constexpr int KC = 128;          // K bytes per chunk
constexpr int STAGES = 4;
constexpr int NK = K_DIM / KC;   // 32 chunks
constexpr int NTHREADS = 512;    // 16 warps: 2(M) x 8(N), warp tile 64x32

constexpr int A_BYTES = MT * KC;                      // 16384
constexpr int B_BYTES = NT * KC;                      // 32768
constexpr int OFF_A = 0;
constexpr int OFF_B = STAGES * A_BYTES;               // 65536
constexpr int SMEM_BYTES = OFF_B + STAGES * B_BYTES;  // 196608

// ---------------- device scratch (allocation is forbidden) ----------------
__device__ unsigned char g_xq[(size_t)M_DIM * K_DIM];   // 16 MB fp8 activations
__device__ float         g_xs[M_DIM];                   // per-token scales
__device__ unsigned char g_wq[(size_t)N_DIM * K_DIM];   // 64 MB fp8 weights

// ---------------- PTX helpers (legal at plain sm_103) ----------------
DI uint32_t smem_u32(const void* p) {
    uint32_t a;
    asm("{ .reg .u64 t; cvta.to.shared.u64 t, %1; cvt.u32.u64 %0, t; }" : "=r"(a) : "l"(p));
    return a;
}
template <int N> DI void cp_wait_group() {
    asm volatile("cp.async.wait_group %0;" :: "n"(N) : "memory");
}
DI void cp_commit() { asm volatile("cp.async.commit_group;" ::: "memory"); }
DI void cp16(uint32_t dst, const void* src) {
    asm volatile("cp.async.cg.shared.global [%0], [%1], 16;" :: "r"(dst), "l"(src) : "memory");
}
DI uint32_t sw128(uint32_t off) { return off ^ ((off >> 3) & 0x70); }
DI uint8_t f2e4m3(float v) { return (uint8_t)__nv_cvt_float_to_fp8(v, __NV_SATFINITE, __NV_E4M3); }

DI void ldsm_x4(uint32_t* r, uint32_t a) {
    asm volatile("ldmatrix.sync.aligned.m8n8.x4.shared.b16 {%0,%1,%2,%3}, [%4];"
                 : "=r"(r[0]), "=r"(r[1]), "=r"(r[2]), "=r"(r[3]) : "r"(a));
}
DI void mma_fp8(float* d, const uint32_t* a, const uint32_t* b) {
    asm volatile(
        "mma.sync.aligned.m16n8k32.row.col.f32.e4m3.e4m3.f32 "
        "{%0,%1,%2,%3}, {%4,%5,%6,%7}, {%8,%9}, {%0,%1,%2,%3};"
        : "+f"(d[0]), "+f"(d[1]), "+f"(d[2]), "+f"(d[3])
        : "r"(a[0]), "r"(a[1]), "r"(a[2]), "r"(a[3]), "r"(b[0]), "r"(b[1]));
}

// ---------------- kernel 1: fused dynamic-quant(x) + repack(w) ----------------
// blocks [0, M_DIM)            : per-token quantization of x (one row per block)
// blocks [M_DIM, M_DIM+WBLK)   : exact fp32 -> e4m3 repack of weight
constexpr int WBLK = (int)(((size_t)N_DIM * K_DIM / 4) / 256);   // 65536

__global__ void __launch_bounds__(256) quant_fused_kernel(
    const float* __restrict__ x, const float* __restrict__ w)
{
    if (blockIdx.x < M_DIM) {
        int row = blockIdx.x;
        const float4* xr = reinterpret_cast<const float4*>(x + (size_t)row * K_DIM);
        float4 v[4];
        float amax = 0.f;
#pragma unroll
        for (int j = 0; j < 4; j++) {
            v[j] = xr[threadIdx.x + j * 256];
            amax = fmaxf(amax, fmaxf(fmaxf(fabsf(v[j].x), fabsf(v[j].y)),
                                     fmaxf(fabsf(v[j].z), fabsf(v[j].w))));
        }
#pragma unroll
        for (int o = 16; o; o >>= 1) amax = fmaxf(amax, __shfl_xor_sync(0xFFFFFFFFu, amax, o));
        __shared__ float wmax[8];
        __shared__ float s_scale;
        if ((threadIdx.x & 31) == 0) wmax[threadIdx.x >> 5] = amax;
        __syncthreads();
        if (threadIdx.x == 0) {
            float m = wmax[0];
#pragma unroll
            for (int i = 1; i < 8; i++) m = fmaxf(m, wmax[i]);
            float sc = fmaxf(__fdiv_rn(m, 448.0f), 1e-12f);
            g_xs[row] = sc;
            s_scale = sc;
        }
        __syncthreads();
        float sc = s_scale;
        uint32_t* outp = reinterpret_cast<uint32_t*>(g_xq + (size_t)row * K_DIM);
#pragma unroll
        for (int j = 0; j < 4; j++) {
            uint32_t p = (uint32_t)f2e4m3(__fdiv_rn(v[j].x, sc))
                       | ((uint32_t)f2e4m3(__fdiv_rn(v[j].y, sc)) << 8)
                       | ((uint32_t)f2e4m3(__fdiv_rn(v[j].z, sc)) << 16)
                       | ((uint32_t)f2e4m3(__fdiv_rn(v[j].w, sc)) << 24);
            outp[threadIdx.x + j * 256] = p;
        }
    } else {
        size_t i = (size_t)(blockIdx.x - M_DIM) * 256 + threadIdx.x;   // float4 index
        float4 v = reinterpret_cast<const float4*>(w)[i];
        uint32_t p = (uint32_t)f2e4m3(v.x)
                   | ((uint32_t)f2e4m3(v.y) << 8)
                   | ((uint32_t)f2e4m3(v.z) << 16)
                   | ((uint32_t)f2e4m3(v.w) << 24);
        reinterpret_cast<uint32_t*>(g_wq)[i] = p;
    }
}

// ---------------- kernel 2: fp8 mma.sync GEMM + fused dequant/bias ----------------
__global__ void __launch_bounds__(NTHREADS, 1) gemm_kernel(
    const float* __restrict__ wscale, const float* __restrict__ bias,
    float* __restrict__ out)
{
    extern __shared__ char smem[];
    uint32_t sb = smem_u32(smem);
    int tid = threadIdx.x;
    int m0 = blockIdx.x * MT;
    int n0 = blockIdx.y * NT;
    const unsigned char* gA = g_xq + (size_t)m0 * K_DIM;
    const unsigned char* gB = g_wq + (size_t)n0 * K_DIM;
    int lane = tid & 31, wid = tid >> 5;
    int wm = wid & 1;        // warp M index (0..1)
    int wn = wid >> 1;       // warp N index (0..7)

    // ---- per-thread cp.async offsets, precomputed once ----
    // i = 0,1 -> A tile rows (tid + i*512 in [0,1024)), i = 2..5 -> B tile rows
    uint32_t dstoff[6];
    uint32_t srcoff[6];
#pragma unroll
    for (int i = 0; i < 6; i++) {
        int idx = tid + i * NTHREADS;
        bool isA = idx < 1024;
        int loc = isA ? idx : idx - 1024;
        int row = loc >> 3;
        int c = loc & 7;
        dstoff[i] = (isA ? OFF_A : OFF_B) + sw128((uint32_t)(row * 128 + c * 16));
        srcoff[i] = (uint32_t)(row * K_DIM + c * 16);
    }
    auto load_chunk = [&](int s, int kc) {
#pragma unroll
        for (int i = 0; i < 2; i++)
            cp16(sb + (uint32_t)(s * A_BYTES) + dstoff[i], gA + (size_t)kc * KC + srcoff[i]);
#pragma unroll
        for (int i = 2; i < 6; i++)
            cp16(sb + (uint32_t)(s * B_BYTES) + dstoff[i], gB + (size_t)kc * KC + srcoff[i]);
        cp_commit();
    };

    // ---- ldmatrix per-lane addressing (fp8 tiles viewed as b16) ----
    // A: m16k32 fragments, 4 per ks (am = 0..3 over 64 rows)
    int rowA = wm * 64 + ((lane >> 3) & 1) * 8 + (lane & 7);
    uint32_t kA = ((uint32_t)(lane >> 4)) * 16;
    uint32_t xrA = (uint32_t)((rowA & 7) * 16);
    // B: x4 ldmatrix covers TWO n8 blocks (16 rows): lanes 0-15 -> first n8, 16-31 -> second
    int rowB = wn * 32 + (lane & 7) + ((lane >> 4) & 1) * 8;
    uint32_t kB = ((uint32_t)((lane >> 3) & 1)) * 16;
    uint32_t xrB = (uint32_t)((lane & 7) * 16);

    float d[4][4][4];
#pragma unroll
    for (int i = 0; i < 4; i++)
#pragma unroll
        for (int j = 0; j < 4; j++)
#pragma unroll
            for (int k = 0; k < 4; k++) d[i][j][k] = 0.f;

    // ---- prologue: stages 0..2 <- chunks 0..2 ----
#pragma unroll
    for (int i = 0; i < STAGES - 1; i++) load_chunk(i, i);

    for (int kc = 0; kc < NK; kc++) {
        // make chunk kc resident (this thread's group), then publish to all warps
        if (kc < NK - 2)       cp_wait_group<2>();
        else if (kc == NK - 2) cp_wait_group<1>();
        else                   cp_wait_group<0>();
        __syncthreads();   // also guarantees everyone finished compute of kc-1

        // prefetch chunk kc+3 into stage (kc+3)%4 (safe: distinct from kc,kc+1,kc+2)
        if (kc + 3 < NK) load_chunk((kc + 3) & 3, kc + 3);

        int s = kc & 3;
        uint32_t aBase = sb + OFF_A + (uint32_t)(s * A_BYTES) + (uint32_t)rowA * 128;
        uint32_t bBase = sb + OFF_B + (uint32_t)(s * B_BYTES) + (uint32_t)rowB * 128;

        uint32_t a[2][4];     // A fragment double buffer (parity on am)
        uint32_t b[2][8];     // B fragments for one ks (4 n8 blocks), double buffer

        uint32_t colA0 = kA ^ xrA;
        uint32_t colB0 = kB ^ xrB;
        ldsm_x4(&b[0][0], bBase + colB0);            // n8 blocks 0,1
        ldsm_x4(&b[0][4], bBase + 2048 + colB0);     // n8 blocks 2,3
        ldsm_x4(a[0], aBase + colA0);                // ks=0, am=0

#pragma unroll
        for (int ks = 0; ks < 4; ks++) {
            int cb = ks & 1;
            uint32_t colA = (kA + (uint32_t)ks * 32) ^ xrA;
#pragma unroll
            for (int am = 0; am < 4; am++) {
                int pa = am & 1;
                // prefetch next fragments under the MMAs
                if (am < 3) {
                    ldsm_x4(a[pa ^ 1], aBase + (uint32_t)((am + 1) * 2048) + colA);
                } else if (ks < 3) {
                    uint32_t colAn = (kA + (uint32_t)(ks + 1) * 32) ^ xrA;
                    uint32_t colBn = (kB + (uint32_t)(ks + 1) * 32) ^ xrB;
                    ldsm_x4(&b[cb ^ 1][0], bBase + colBn);
                    ldsm_x4(&b[cb ^ 1][4], bBase + 2048 + colBn);
                    ldsm_x4(a[pa ^ 1], aBase + colAn);
                }
                mma_fp8(d[am][0], a[pa], &b[cb][0]);
                mma_fp8(d[am][1], a[pa], &b[cb][2]);
                mma_fp8(d[am][2], a[pa], &b[cb][4]);
                mma_fp8(d[am][3], a[pa], &b[cb][6]);
            }
        }
    }

    // ---- epilogue: fused per-token * per-channel dequant + bias ----
    int g = lane >> 2, tig = lane & 3;
#pragma unroll
    for (int am = 0; am < 4; am++) {
        int r0 = m0 + wm * 64 + am * 16 + g;
        int r1 = r0 + 8;
        float xs0 = g_xs[r0], xs1 = g_xs[r1];
        float* p0 = out + (size_t)r0 * N_DIM;
        float* p1 = out + (size_t)r1 * N_DIM;
#pragma unroll
        for (int bn = 0; bn < 4; bn++) {
            int c = n0 + wn * 32 + bn * 8 + tig * 2;
            float2 ws = *reinterpret_cast<const float2*>(wscale + c);
            float2 bb = *reinterpret_cast<const float2*>(bias + c);
            float2 o0, o1;
            o0.x = d[am][bn][0] * xs0 * ws.x + bb.x;
            o0.y = d[am][bn][1] * xs0 * ws.y + bb.y;
            o1.x = d[am][bn][2] * xs1 * ws.x + bb.x;
            o1.y = d[am][bn][3] * xs1 * ws.y + bb.y;
            *reinterpret_cast<float2*>(p0 + c) = o0;
            *reinterpret_cast<float2*>(p1 + c) = o1;
        }
    }
}

// ---------------- launch ----------------
extern "C" void kernel_launch(void* const* d_in, const int* in_sizes, int n_in,
                              void* d_out, int out_size) {
    const float* x  = (const float*)d_in[0];
    const float* w  = (const float*)d_in[1];
    const float* ws = (const float*)d_in[2];
    const float* b  = (const float*)d_in[3];
    float* out = (float*)d_out;

    quant_fused_kernel<<<M_DIM + WBLK, 256>>>(x, w);

    cudaFuncSetAttribute(gemm_kernel, cudaFuncAttributeMaxDynamicSharedMemorySize, SMEM_BYTES);
    dim3 grid(M_DIM / MT, N_DIM / NT);   // (32, 64); x-fastest => B-tile reuse in L2
    gemm_kernel<<<grid, NTHREADS, SMEM_BYTES>>>(ws, b, out);
}

// round 6
// speedup vs baseline: 1.0519x; 1.0519x over previous
#include <cuda_runtime.h>
#include <cuda_fp8.h>
#include <stdint.h>

#define DI __device__ __forceinline__

// ---------------- problem constants ----------------
constexpr int M_DIM = 4096;
constexpr int K_DIM = 4096;
constexpr int N_DIM = 16384;

// ---------------- GEMM tiling ----------------
constexpr int MT = 128;          // CTA M tile
constexpr int NT = 256;          // CTA N tile
constexpr int KC = 128;          // K bytes per chunk
constexpr int STAGES = 4;
constexpr int NK = K_DIM / KC;   // 32 chunks
constexpr int NTHREADS = 256;    // 8 warps: 2(M) x 4(N), warp tile 64x64

constexpr int A_BYTES = MT * KC;                      // 16384
constexpr int B_BYTES = NT * KC;                      // 32768
constexpr int OFF_A = 0;
constexpr int OFF_B = STAGES * A_BYTES;               // 65536
constexpr int SMEM_BYTES = OFF_B + STAGES * B_BYTES;  // 196608

// ---------------- device scratch (allocation is forbidden) ----------------
__device__ unsigned char g_xq[(size_t)M_DIM * K_DIM];   // 16 MB fp8 activations
__device__ float         g_xs[M_DIM];                   // per-token scales
__device__ unsigned char g_wq[(size_t)N_DIM * K_DIM];   // 64 MB fp8 weights

// ---------------- PTX helpers (legal at plain sm_103) ----------------
DI uint32_t smem_u32(const void* p) {
    uint32_t a;
    asm("{ .reg .u64 t; cvta.to.shared.u64 t, %1; cvt.u32.u64 %0, t; }" : "=r"(a) : "l"(p));
    return a;
}
template <int N> DI void cp_wait_group() {
    asm volatile("cp.async.wait_group %0;" :: "n"(N) : "memory");
}
DI void cp_commit() { asm volatile("cp.async.commit_group;" ::: "memory"); }
DI void cp16(uint32_t dst, const void* src) {
    asm volatile("cp.async.cg.shared.global [%0], [%1], 16;" :: "r"(dst), "l"(src) : "memory");
}
DI uint32_t sw128(uint32_t off) { return off ^ ((off >> 3) & 0x70); }
DI uint8_t f2e4m3(float v) { return (uint8_t)__nv_cvt_float_to_fp8(v, __NV_SATFINITE, __NV_E4M3); }

DI void ldsm_x4(uint32_t* r, uint32_t a) {
    asm volatile("ldmatrix.sync.aligned.m8n8.x4.shared.b16 {%0,%1,%2,%3}, [%4];"
                 : "=r"(r[0]), "=r"(r[1]), "=r"(r[2]), "=r"(r[3]) : "r"(a));
}
DI void mma_fp8(float* d, const uint32_t* a, const uint32_t* b) {
    asm volatile(
        "mma.sync.aligned.m16n8k32.row.col.f32.e4m3.e4m3.f32 "
        "{%0,%1,%2,%3}, {%4,%5,%6,%7}, {%8,%9}, {%0,%1,%2,%3};"
        : "+f"(d[0]), "+f"(d[1]), "+f"(d[2]), "+f"(d[3])
        : "r"(a[0]), "r"(a[1]), "r"(a[2]), "r"(a[3]), "r"(b[0]), "r"(b[1]));
}

// ---------------- kernel 1: fused dynamic-quant(x) + repack(w) ----------------
constexpr int WBLK = (int)(((size_t)N_DIM * K_DIM / 4) / 256);   // 65536

__global__ void __launch_bounds__(256) quant_fused_kernel(
    const float* __restrict__ x, const float* __restrict__ w)
{
    if (blockIdx.x < M_DIM) {
        int row = blockIdx.x;
        const float4* xr = reinterpret_cast<const float4*>(x + (size_t)row * K_DIM);
        float4 v[4];
        float amax = 0.f;
#pragma unroll
        for (int j = 0; j < 4; j++) {
            v[j] = xr[threadIdx.x + j * 256];
            amax = fmaxf(amax, fmaxf(fmaxf(fabsf(v[j].x), fabsf(v[j].y)),
                                     fmaxf(fabsf(v[j].z), fabsf(v[j].w))));
        }
#pragma unroll
        for (int o = 16; o; o >>= 1) amax = fmaxf(amax, __shfl_xor_sync(0xFFFFFFFFu, amax, o));
        __shared__ float wmax[8];
        __shared__ float s_scale;
        if ((threadIdx.x & 31) == 0) wmax[threadIdx.x >> 5] = amax;
        __syncthreads();
        if (threadIdx.x == 0) {
            float m = wmax[0];
#pragma unroll
            for (int i = 1; i < 8; i++) m = fmaxf(m, wmax[i]);
            float sc = fmaxf(__fdiv_rn(m, 448.0f), 1e-12f);
            g_xs[row] = sc;
            s_scale = sc;
        }
        __syncthreads();
        float sc = s_scale;
        uint32_t* outp = reinterpret_cast<uint32_t*>(g_xq + (size_t)row * K_DIM);
#pragma unroll
        for (int j = 0; j < 4; j++) {
            uint32_t p = (uint32_t)f2e4m3(__fdiv_rn(v[j].x, sc))
                       | ((uint32_t)f2e4m3(__fdiv_rn(v[j].y, sc)) << 8)
                       | ((uint32_t)f2e4m3(__fdiv_rn(v[j].z, sc)) << 16)
                       | ((uint32_t)f2e4m3(__fdiv_rn(v[j].w, sc)) << 24);
            outp[threadIdx.x + j * 256] = p;
        }
    } else {
        size_t i = (size_t)(blockIdx.x - M_DIM) * 256 + threadIdx.x;   // float4 index
        float4 v = reinterpret_cast<const float4*>(w)[i];
        uint32_t p = (uint32_t)f2e4m3(v.x)
                   | ((uint32_t)f2e4m3(v.y) << 8)
                   | ((uint32_t)f2e4m3(v.z) << 16)
                   | ((uint32_t)f2e4m3(v.w) << 24);
        reinterpret_cast<uint32_t*>(g_wq)[i] = p;
    }
}

// ---------------- kernel 2: fp8 mma.sync GEMM + fused dequant/bias ----------------
// 8 warps, warp tile 64(M) x 64(N). Accum d[4 am][8 bn][4] = 128 regs/thread.
__global__ void __launch_bounds__(NTHREADS, 1) gemm_kernel(
    const float* __restrict__ wscale, const float* __restrict__ bias,
    float* __restrict__ out)
{
    extern __shared__ char smem[];
    uint32_t sb = smem_u32(smem);
    int tid = threadIdx.x;
    int m0 = blockIdx.x * MT;
    int n0 = blockIdx.y * NT;
    const unsigned char* gA = g_xq + (size_t)m0 * K_DIM;
    const unsigned char* gB = g_wq + (size_t)n0 * K_DIM;
    int lane = tid & 31, wid = tid >> 5;
    int wm = wid & 1;        // warp M index (0..1)
    int wn = wid >> 1;       // warp N index (0..3)

    // ---- cp.async: 3072 x 16B per chunk / 256 threads = 12 per thread ----
    // thread covers 12 (row, col16) slots; rows 0..1023 = A(2 rows per thread..),
    // computed inline per chunk (cheap: adds only).
    int ldrow = tid >> 3;          // 0..31
    int ldcol = tid & 7;           // 0..7 (16B columns)
    uint32_t ldst = sw128((uint32_t)((ldrow & 31) * 128 + ldcol * 16));

    auto load_chunk = [&](int s, int kc) {
        const unsigned char* pa = gA + (size_t)kc * KC;
        const unsigned char* pb = gB + (size_t)kc * KC;
        uint32_t sa = sb + OFF_A + (uint32_t)(s * A_BYTES) + ldst;
        uint32_t sbb = sb + OFF_B + (uint32_t)(s * B_BYTES) + ldst;
        const unsigned char* qa = pa + (size_t)ldrow * K_DIM + ldcol * 16;
        const unsigned char* qb = pb + (size_t)ldrow * K_DIM + ldcol * 16;
#pragma unroll
        for (int i = 0; i < 4; i++)     // A: 128 rows in 4 groups of 32
            cp16(sa + (uint32_t)(i * 32 * 128), qa + (size_t)(i * 32) * K_DIM);
#pragma unroll
        for (int i = 0; i < 8; i++)     // B: 256 rows in 8 groups of 32
            cp16(sbb + (uint32_t)(i * 32 * 128), qb + (size_t)(i * 32) * K_DIM);
        cp_commit();
    };

    // ---- ldmatrix per-lane addressing (fp8 tiles viewed as b16) ----
    // A: m16k32 fragment via x4 (16 rows x 32B)
    int rowA = wm * 64 + ((lane >> 3) & 1) * 8 + (lane & 7);
    uint32_t kA = ((uint32_t)(lane >> 4)) * 16;
    uint32_t xrA = (uint32_t)((rowA & 7) * 16);
    // B: x4 covers TWO n8 blocks (16 rows; lanes 0-15 first block, 16-31 second)
    int rowB = wn * 64 + (lane & 7) + ((lane >> 4) & 1) * 8;
    uint32_t kB = ((uint32_t)((lane >> 3) & 1)) * 16;
    uint32_t xrB = (uint32_t)((lane & 7) * 16);

    float d[4][8][4];
#pragma unroll
    for (int i = 0; i < 4; i++)
#pragma unroll
        for (int j = 0; j < 8; j++)
#pragma unroll
            for (int k = 0; k < 4; k++) d[i][j][k] = 0.f;

    // ---- prologue ----
#pragma unroll
    for (int i = 0; i < STAGES - 1; i++) load_chunk(i, i);

    for (int kc = 0; kc < NK; kc++) {
        // issue chunk kc+3 (stage reuse is safe: trailing sync of prev iter)
        if (kc + 3 < NK) { load_chunk((kc + 3) & 3, kc + 3); cp_wait_group<3>(); }
        else             { cp_wait_group<0>(); }
        __syncthreads();                      // stage kc visible to all warps

        int s = kc & 3;
        uint32_t aBase = sb + OFF_A + (uint32_t)(s * A_BYTES) + (uint32_t)rowA * 128;
        uint32_t bBase = sb + OFF_B + (uint32_t)(s * B_BYTES) + (uint32_t)rowB * 128;

#pragma unroll
        for (int ks = 0; ks < 4; ks++) {
            uint32_t colA = (kA + (uint32_t)ks * 32) ^ xrA;
            uint32_t colB = (kB + (uint32_t)ks * 32) ^ xrB;
            uint32_t a[4][4];
            uint32_t b[4][4];    // 4 x4 loads = 8 n8 blocks
#pragma unroll
            for (int i = 0; i < 4; i++) ldsm_x4(a[i], aBase + (uint32_t)(i * 2048) + colA);
#pragma unroll
            for (int i = 0; i < 4; i++) ldsm_x4(b[i], bBase + (uint32_t)(i * 2048) + colB);
#pragma unroll
            for (int am = 0; am < 4; am++)
#pragma unroll
                for (int bn = 0; bn < 8; bn++)
                    mma_fp8(d[am][bn], a[am], &b[bn >> 1][(bn & 1) * 2]);
        }
        __syncthreads();                      // protect stage before overwrite
    }

    // ---- epilogue: fused per-token * per-channel dequant + bias ----
    int g = lane >> 2, tig = lane & 3;
#pragma unroll
    for (int am = 0; am < 4; am++) {
        int r0 = m0 + wm * 64 + am * 16 + g;
        int r1 = r0 + 8;
        float xs0 = g_xs[r0], xs1 = g_xs[r1];
        float* p0 = out + (size_t)r0 * N_DIM;
        float* p1 = out + (size_t)r1 * N_DIM;
#pragma unroll
        for (int bn = 0; bn < 8; bn++) {
            int c = n0 + wn * 64 + bn * 8 + tig * 2;
            float2 ws = *reinterpret_cast<const float2*>(wscale + c);
            float2 bb = *reinterpret_cast<const float2*>(bias + c);
            float2 o0, o1;
            o0.x = d[am][bn][0] * xs0 * ws.x + bb.x;
            o0.y = d[am][bn][1] * xs0 * ws.y + bb.y;
            o1.x = d[am][bn][2] * xs1 * ws.x + bb.x;
            o1.y = d[am][bn][3] * xs1 * ws.y + bb.y;
            *reinterpret_cast<float2*>(p0 + c) = o0;
            *reinterpret_cast<float2*>(p1 + c) = o1;
        }
    }
}

// ---------------- launch ----------------
extern "C" void kernel_launch(void* const* d_in, const int* in_sizes, int n_in,
                              void* d_out, int out_size) {
    const float* x  = (const float*)d_in[0];
    const float* w  = (const float*)d_in[1];
    const float* ws = (const float*)d_in[2];
    const float* b  = (const float*)d_in[3];
    float* out = (float*)d_out;

    quant_fused_kernel<<<M_DIM + WBLK, 256>>>(x, w);

    cudaFuncSetAttribute(gemm_kernel, cudaFuncAttributeMaxDynamicSharedMemorySize, SMEM_BYTES);
    dim3 grid(M_DIM / MT, N_DIM / NT);   // (32, 64); x-fastest => B-tile reuse in L2
    gemm_kernel<<<grid, NTHREADS, SMEM_BYTES>>>(ws, b, out);
}

// round 9
// speedup vs baseline: 1.1597x; 1.1025x over previous
#include <cuda_runtime.h>
#include <cuda_fp8.h>
#include <stdint.h>

#define DI __device__ __forceinline__

// ---------------- problem constants ----------------
constexpr int M_DIM = 4096;
constexpr int K_DIM = 4096;
constexpr int N_DIM = 16384;

// ---------------- GEMM tiling ----------------
constexpr int MT = 128;          // CTA M tile
constexpr int NT = 256;          // CTA N tile
constexpr int KC = 128;          // K bytes per chunk
constexpr int STAGES = 4;
constexpr int NK = K_DIM / KC;   // 32 chunks
constexpr int NTHREADS = 256;    // 8 warps: 2(M) x 4(N), warp tile 64x64

constexpr int A_BYTES = MT * KC;                      // 16384
constexpr int B_BYTES = NT * KC;                      // 32768
constexpr int OFF_A = 0;
constexpr int OFF_B = STAGES * A_BYTES;               // 65536
constexpr int SMEM_BYTES = OFF_B + STAGES * B_BYTES;  // 196608

// ---------------- device scratch (allocation is forbidden) ----------------
__device__ unsigned char g_xq[(size_t)M_DIM * K_DIM];   // 16 MB fp8 activations
__device__ float         g_xs[M_DIM];                   // per-token scales
__device__ unsigned char g_wq[(size_t)N_DIM * K_DIM];   // 64 MB fp8 weights

// ---------------- PTX helpers (legal at plain sm_103) ----------------
DI uint32_t smem_u32(const void* p) {
    uint32_t a;
    asm("{ .reg .u64 t; cvta.to.shared.u64 t, %1; cvt.u32.u64 %0, t; }" : "=r"(a) : "l"(p));
    return a;
}
template <int N> DI void cp_wait_group() {
    asm volatile("cp.async.wait_group %0;" :: "n"(N) : "memory");
}
DI void cp_commit() { asm volatile("cp.async.commit_group;" ::: "memory"); }
DI void cp16(uint32_t dst, const void* src) {
    asm volatile("cp.async.cg.shared.global [%0], [%1], 16;" :: "r"(dst), "l"(src) : "memory");
}
DI uint32_t sw128(uint32_t off) { return off ^ ((off >> 3) & 0x70); }
DI uint8_t f2e4m3(float v) { return (uint8_t)__nv_cvt_float_to_fp8(v, __NV_SATFINITE, __NV_E4M3); }

DI void ldsm_x4(uint32_t* r, uint32_t a) {
    asm volatile("ldmatrix.sync.aligned.m8n8.x4.shared.b16 {%0,%1,%2,%3}, [%4];"
                 : "=r"(r[0]), "=r"(r[1]), "=r"(r[2]), "=r"(r[3]) : "r"(a));
}
DI void mma_fp8(float* d, const uint32_t* a, const uint32_t* b) {
    asm volatile(
        "mma.sync.aligned.m16n8k32.row.col.f32.e4m3.e4m3.f32 "
        "{%0,%1,%2,%3}, {%4,%5,%6,%7}, {%8,%9}, {%0,%1,%2,%3};"
        : "+f"(d[0]), "+f"(d[1]), "+f"(d[2]), "+f"(d[3])
        : "r"(a[0]), "r"(a[1]), "r"(a[2]), "r"(a[3]), "r"(b[0]), "r"(b[1]));
}

// ---------------- kernel 1: fused dynamic-quant(x) + repack(w) ----------------
constexpr int WBLK = (int)(((size_t)N_DIM * K_DIM / 4) / 256);   // 65536

__global__ void __launch_bounds__(256) quant_fused_kernel(
    const float* __restrict__ x, const float* __restrict__ w)
{
    if (blockIdx.x < M_DIM) {
        int row = blockIdx.x;
        const float4* xr = reinterpret_cast<const float4*>(x + (size_t)row * K_DIM);
        float4 v[4];
        float amax = 0.f;
#pragma unroll
        for (int j = 0; j < 4; j++) {
            v[j] = xr[threadIdx.x + j * 256];
            amax = fmaxf(amax, fmaxf(fmaxf(fabsf(v[j].x), fabsf(v[j].y)),
                                     fmaxf(fabsf(v[j].z), fabsf(v[j].w))));
        }
#pragma unroll
        for (int o = 16; o; o >>= 1) amax = fmaxf(amax, __shfl_xor_sync(0xFFFFFFFFu, amax, o));
        __shared__ float wmax[8];
        __shared__ float s_scale;
        if ((threadIdx.x & 31) == 0) wmax[threadIdx.x >> 5] = amax;
        __syncthreads();
        if (threadIdx.x == 0) {
            float m = wmax[0];
#pragma unroll
            for (int i = 1; i < 8; i++) m = fmaxf(m, wmax[i]);
            float sc = fmaxf(__fdiv_rn(m, 448.0f), 1e-12f);
            g_xs[row] = sc;
            s_scale = sc;
        }
        __syncthreads();
        float sc = s_scale;
        uint32_t* outp = reinterpret_cast<uint32_t*>(g_xq + (size_t)row * K_DIM);
#pragma unroll
        for (int j = 0; j < 4; j++) {
            uint32_t p = (uint32_t)f2e4m3(__fdiv_rn(v[j].x, sc))
                       | ((uint32_t)f2e4m3(__fdiv_rn(v[j].y, sc)) << 8)
                       | ((uint32_t)f2e4m3(__fdiv_rn(v[j].z, sc)) << 16)
                       | ((uint32_t)f2e4m3(__fdiv_rn(v[j].w, sc)) << 24);
            outp[threadIdx.x + j * 256] = p;
        }
    } else {
        size_t i = (size_t)(blockIdx.x - M_DIM) * 256 + threadIdx.x;   // float4 index
        float4 v = reinterpret_cast<const float4*>(w)[i];
        uint32_t p = (uint32_t)f2e4m3(v.x)
                   | ((uint32_t)f2e4m3(v.y) << 8)
                   | ((uint32_t)f2e4m3(v.z) << 16)
                   | ((uint32_t)f2e4m3(v.w) << 24);
        reinterpret_cast<uint32_t*>(g_wq)[i] = p;
    }
}

// ---------------- kernel 2: fp8 mma.sync GEMM + fused dequant/bias ----------------
// 8 warps, warp tile 64(M) x 64(N). Register-disciplined inner loop:
// ks loop NOT unrolled so only one ks' fragments are live (~180 regs total).
__global__ void __launch_bounds__(NTHREADS, 1) gemm_kernel(
    const float* __restrict__ wscale, const float* __restrict__ bias,
    float* __restrict__ out)
{
    extern __shared__ char smem[];
    uint32_t sb = smem_u32(smem);
    int tid = threadIdx.x;
    int m0 = blockIdx.x * MT;
    int n0 = blockIdx.y * NT;
    const unsigned char* gA = g_xq + (size_t)m0 * K_DIM;
    const unsigned char* gB = g_wq + (size_t)n0 * K_DIM;
    int lane = tid & 31, wid = tid >> 5;
    int wm = wid & 1;        // warp M index (0..1)
    int wn = wid >> 1;       // warp N index (0..3)

    // ---- cp.async: 3072 x 16B per chunk / 256 threads = 12 per thread ----
    int ldrow = tid >> 3;          // 0..31
    int ldcol = tid & 7;           // 0..7 (16B columns)
    uint32_t ldst = sw128((uint32_t)(ldrow * 128 + ldcol * 16));

    auto load_chunk = [&](int s, int kc) {
        uint32_t sa = sb + OFF_A + (uint32_t)(s * A_BYTES) + ldst;
        uint32_t sbb = sb + OFF_B + (uint32_t)(s * B_BYTES) + ldst;
        const unsigned char* qa = gA + (size_t)kc * KC + (size_t)ldrow * K_DIM + ldcol * 16;
        const unsigned char* qb = gB + (size_t)kc * KC + (size_t)ldrow * K_DIM + ldcol * 16;
#pragma unroll
        for (int i = 0; i < 4; i++)     // A: 128 rows in 4 groups of 32
            cp16(sa + (uint32_t)(i * 32 * 128), qa + (size_t)(i * 32) * K_DIM);
#pragma unroll
        for (int i = 0; i < 8; i++)     // B: 256 rows in 8 groups of 32
            cp16(sbb + (uint32_t)(i * 32 * 128), qb + (size_t)(i * 32) * K_DIM);
        cp_commit();
    };

    // ---- ldmatrix per-lane addressing (fp8 tiles viewed as b16) ----
    int rowA = wm * 64 + ((lane >> 3) & 1) * 8 + (lane & 7);
    uint32_t kA = ((uint32_t)(lane >> 4)) * 16;
    uint32_t xrA = (uint32_t)((rowA & 7) * 16);
    int rowB = wn * 64 + (lane & 7) + ((lane >> 4) & 1) * 8;
    uint32_t kB = ((uint32_t)((lane >> 3) & 1)) * 16;
    uint32_t xrB = (uint32_t)((lane & 7) * 16);

    float d[4][8][4];
#pragma unroll
    for (int i = 0; i < 4; i++)
#pragma unroll
        for (int j = 0; j < 8; j++)
#pragma unroll
            for (int k = 0; k < 4; k++) d[i][j][k] = 0.f;

    // ---- prologue ----
#pragma unroll
    for (int i = 0; i < STAGES - 1; i++) load_chunk(i, i);

#pragma unroll 1
    for (int kc = 0; kc < NK; kc++) {
        // prefetch chunk kc+3 into stage (kc-1)&3 (protected by trailing sync)
        if (kc + 3 < NK) { load_chunk((kc + 3) & 3, kc + 3); cp_wait_group<3>(); }
        else             { cp_wait_group<0>(); }
        __syncthreads();                      // stage kc visible to all warps

        int s = kc & 3;
        uint32_t aBase = sb + OFF_A + (uint32_t)(s * A_BYTES) + (uint32_t)rowA * 128;
        uint32_t bBase = sb + OFF_B + (uint32_t)(s * B_BYTES) + (uint32_t)rowB * 128;

#pragma unroll 1                              // CRITICAL: one ks live at a time
        for (int ks = 0; ks < 4; ks++) {
            uint32_t colA = (kA + (uint32_t)ks * 32) ^ xrA;
            uint32_t colB = (kB + (uint32_t)ks * 32) ^ xrB;
            uint32_t a[4][4];
#pragma unroll
            for (int i = 0; i < 4; i++) ldsm_x4(a[i], aBase + (uint32_t)(i * 2048) + colA);
#pragma unroll
            for (int i = 0; i < 4; i++) {     // 4 b-loads, each feeding 8 MMAs
                uint32_t b[4];
                ldsm_x4(b, bBase + (uint32_t)(i * 2048) + colB);
#pragma unroll
                for (int am = 0; am < 4; am++) {
                    mma_fp8(d[am][2 * i + 0], a[am], &b[0]);
                    mma_fp8(d[am][2 * i + 1], a[am], &b[2]);
                }
            }
        }
        __syncthreads();                      // protect stage before overwrite
    }

    // ---- epilogue: fused per-token * per-channel dequant + bias ----
    int g = lane >> 2, tig = lane & 3;
#pragma unroll
    for (int am = 0; am < 4; am++) {
        int r0 = m0 + wm * 64 + am * 16 + g;
        int r1 = r0 + 8;
        float xs0 = g_xs[r0], xs1 = g_xs[r1];
        float* p0 = out + (size_t)r0 * N_DIM;
        float* p1 = out + (size_t)r1 * N_DIM;
#pragma unroll
        for (int bn = 0; bn < 8; bn++) {
            int c = n0 + wn * 64 + bn * 8 + tig * 2;
            float2 ws = *reinterpret_cast<const float2*>(wscale + c);
            float2 bb = *reinterpret_cast<const float2*>(bias + c);
            float2 o0, o1;
            o0.x = d[am][bn][0] * xs0 * ws.x + bb.x;
            o0.y = d[am][bn][1] * xs0 * ws.y + bb.y;
            o1.x = d[am][bn][2] * xs1 * ws.x + bb.x;
            o1.y = d[am][bn][3] * xs1 * ws.y + bb.y;
            *reinterpret_cast<float2*>(p0 + c) = o0;
            *reinterpret_cast<float2*>(p1 + c) = o1;
        }
    }
}

// ---------------- launch ----------------
extern "C" void kernel_launch(void* const* d_in, const int* in_sizes, int n_in,
                              void* d_out, int out_size) {
    const float* x  = (const float*)d_in[0];
    const float* w  = (const float*)d_in[1];
    const float* ws = (const float*)d_in[2];
    const float* b  = (const float*)d_in[3];
    float* out = (float*)d_out;

    quant_fused_kernel<<<M_DIM + WBLK, 256>>>(x, w);

    cudaFuncSetAttribute(gemm_kernel, cudaFuncAttributeMaxDynamicSharedMemorySize, SMEM_BYTES);
    dim3 grid(M_DIM / MT, N_DIM / NT);   // (32, 64); x-fastest => B-tile reuse in L2
    gemm_kernel<<<grid, NTHREADS, SMEM_BYTES>>>(ws, b, out);
}